// round 4
// baseline (speedup 1.0000x reference)
#include <cuda_runtime.h>
#include <math.h>

#define LTOK 31744          // 31*32*32
#define DI   128
#define DS   16
#define NXP  36             // DT_RANK + 2*DS
#define LC   32             // scan chunk length
#define NCH  (LTOK/LC)      // 992
#define NT   (LTOK/64)      // 496 token tiles of 64
#define NSEQ (DI*DS)        // 2048
#define GRP  32             // chunks per carry group
#define NGRP (NCH/GRP)      // 31

// ---- scratch layout (floats) ----
#define L64  (LTOK*64)
#define L128 (LTOK*128)
#define L256 (LTOK*256)
#define L32  (LTOK*32)
#define PSZ  (NCH*NSEQ)
#define GSZ  (NGRP*NSEQ)

#define OFF_XIZ   0
#define OFF_XC    (OFF_XIZ + L256)
#define OFF_DELTA (OFF_XC + L128)
#define OFF_BC    (OFF_DELTA + L128)
#define OFF_P     (OFF_BC + L32)
#define OFF_S     (OFF_P + PSZ)
#define OFF_H0    (OFF_S + PSZ)
#define OFF_PA    (OFF_H0 + PSZ)
#define OFF_SA    (OFF_PA + GSZ)
#define OFF_G     (OFF_SA + GSZ)
#define OFF_YZ    (OFF_G + GSZ)
#define OFF_XT2   (OFF_YZ + L128)
#define OFF_HN    (OFF_XT2 + L64)
#define OFF_GG    (OFF_HN + L64)
#define SCRATCH_TOTAL (OFF_GG + L128)

__device__ float g_scratch[SCRATCH_TOTAL];

// ============================================================
// Persistent register-tiled GEMM: Y[L,N] = X[L,K] @ W[K,N]
// LNIN=1: X is raw x in [C=64, L] layout; tile transposed+LayerNormed.
// EPI 0: plain store
// EPI 1: gated FFN1: Y[l,c] = silu(o[l,c]) * o[l,c+128]
// EPI 2: out-proj: v = acc + residual; Y=v; Y2=LN(v)*lw+lb (RTR: R in [C,L])
// EPI 3: final: v = acc + R([L,64]); Y[c*L + l] = v
// ============================================================
template<int K, int N, int RC, int EPI, int LNIN, int RTR>
__global__ void k_gemm(const float* __restrict__ X, const float* __restrict__ W,
                       float* __restrict__ Y, const float* __restrict__ R,
                       const float* __restrict__ lw, const float* __restrict__ lb,
                       float* __restrict__ Y2)
{
    extern __shared__ float sm[];
    float* sW  = sm;                    // K*N
    float* sX  = sm + K * N;            // 64*K  (reused as sT 64x65 in EPI 2/3)
    float* sAux = sm + K * N + 64 * K;  // 64*65
    int tid = threadIdx.x, tx = tid & 31, ty = tid >> 5;

    for (int i = tid; i < K * N; i += 256) sW[i] = W[i];
    __syncthreads();

    for (int tile = blockIdx.x; tile < NT; tile += gridDim.x) {
        int l0 = tile * 64;

        if (LNIN) {
            for (int idx = tid; idx < 4096; idx += 256) {
                int c = idx >> 6, i = idx & 63;
                sAux[i * 65 + c] = X[c * LTOK + l0 + i];
            }
            __syncthreads();
            int r = tid >> 2, q = tid & 3;
            float s = 0.f, ss = 0.f;
            #pragma unroll
            for (int c = q * 16; c < q * 16 + 16; c++) {
                float v = sAux[r * 65 + c]; s += v; ss += v * v;
            }
            s  += __shfl_xor_sync(~0u, s, 1);  ss += __shfl_xor_sync(~0u, ss, 1);
            s  += __shfl_xor_sync(~0u, s, 2);  ss += __shfl_xor_sync(~0u, ss, 2);
            float mu = s * (1.f / 64.f);
            float rs = rsqrtf(ss * (1.f / 64.f) - mu * mu + 1e-5f);
            #pragma unroll
            for (int c = q * 16; c < q * 16 + 16; c++)
                sX[r * 64 + c] = (sAux[r * 65 + c] - mu) * rs * lw[c] + lb[c];
        } else {
            for (int i = tid; i < 64 * K; i += 256) sX[i] = X[l0 * K + i];
        }
        if (EPI >= 2) {
            if (RTR) {
                for (int idx = tid; idx < 4096; idx += 256) {
                    int c = idx >> 6, i = idx & 63;
                    sAux[i * 65 + c] = R[c * LTOK + l0 + i];
                }
            } else {
                for (int idx = tid; idx < 4096; idx += 256) {
                    int r = idx >> 6, c = idx & 63;
                    sAux[r * 65 + c] = R[(l0 + r) * 64 + c];
                }
            }
        }
        __syncthreads();

        float acc[8][RC];
        #pragma unroll
        for (int i = 0; i < 8; i++)
            #pragma unroll
            for (int j = 0; j < RC; j++) acc[i][j] = 0.f;

        #pragma unroll 2
        for (int k4 = 0; k4 < K; k4 += 4) {
            float4 xv[8];
            #pragma unroll
            for (int i = 0; i < 8; i++)
                xv[i] = *reinterpret_cast<const float4*>(&sX[(ty * 8 + i) * K + k4]);
            #pragma unroll
            for (int kk = 0; kk < 4; kk++) {
                float wv[RC];
                #pragma unroll
                for (int j = 0; j < RC; j++) wv[j] = sW[(k4 + kk) * N + tx + 32 * j];
                #pragma unroll
                for (int i = 0; i < 8; i++) {
                    float xs = (kk == 0) ? xv[i].x : (kk == 1) ? xv[i].y
                             : (kk == 2) ? xv[i].z : xv[i].w;
                    #pragma unroll
                    for (int j = 0; j < RC; j++) acc[i][j] = fmaf(xs, wv[j], acc[i][j]);
                }
            }
        }
        __syncthreads();

        if (EPI == 0) {
            #pragma unroll
            for (int i = 0; i < 8; i++)
                #pragma unroll
                for (int j = 0; j < RC; j++)
                    Y[(l0 + ty * 8 + i) * N + tx + 32 * j] = acc[i][j];
        } else if (EPI == 1) {
            #pragma unroll
            for (int i = 0; i < 8; i++)
                #pragma unroll
                for (int j = 0; j < 4; j++) {
                    float g = acc[i][j], v = acc[i][j + 4];
                    float sg = g / (1.f + __expf(-g));
                    Y[(l0 + ty * 8 + i) * 128 + tx + 32 * j] = sg * v;
                }
        } else {
            float* sT = sX;
            #pragma unroll
            for (int i = 0; i < 8; i++)
                #pragma unroll
                for (int j = 0; j < RC; j++) {
                    int row = ty * 8 + i, col = tx + 32 * j;
                    sT[row * 65 + col] = acc[i][j] + sAux[row * 65 + col];
                }
            __syncthreads();
            if (EPI == 2) {
                int r = tid >> 2, q = tid & 3;
                float s = 0.f, ss = 0.f;
                #pragma unroll
                for (int c = q * 16; c < q * 16 + 16; c++) {
                    float v = sT[r * 65 + c]; s += v; ss += v * v;
                }
                s  += __shfl_xor_sync(~0u, s, 1);  ss += __shfl_xor_sync(~0u, ss, 1);
                s  += __shfl_xor_sync(~0u, s, 2);  ss += __shfl_xor_sync(~0u, ss, 2);
                float mu = s * (1.f / 64.f);
                float rs = rsqrtf(ss * (1.f / 64.f) - mu * mu + 1e-5f);
                #pragma unroll
                for (int c = q * 16; c < q * 16 + 16; c++) {
                    float v = sT[r * 65 + c];
                    Y[(l0 + r) * 64 + c]  = v;
                    Y2[(l0 + r) * 64 + c] = (v - mu) * rs * lw[c] + lb[c];
                }
            } else {
                for (int idx = tid; idx < 4096; idx += 256) {
                    int ll = idx & 63, c = idx >> 6;
                    Y[c * LTOK + l0 + ll] = sT[ll * 65 + c];
                }
            }
            __syncthreads();
        }
    }
}

// ============================================================
// conv + relu + xproj + softplus(delta)
// ============================================================
__global__ void k_conv(const float* __restrict__ xiz, const float* __restrict__ cw,
                       const float* __restrict__ Wxp, const float* __restrict__ Wdt,
                       const float* __restrict__ bias,
                       float* __restrict__ xc, float* __restrict__ delta,
                       float* __restrict__ bcout)
{
    extern __shared__ float sm[];
    float* sxc  = sm;               // 64*128
    float* sWx  = sxc + 8192;       // 128*36
    float* sdbl = sWx + 4608;       // 64*36
    float* sWdt = sdbl + 2304;      // 4*128
    float* scw  = sWdt + 512;       // 512
    int tid = threadIdx.x;
    int l0 = blockIdx.x * 64;

    for (int i = tid; i < 4608; i += 256) sWx[i] = Wxp[i];
    for (int i = tid; i < 512; i += 256) { sWdt[i] = Wdt[i]; scw[i] = cw[i]; }
    __syncthreads();

    for (int idx = tid; idx < 8192; idx += 256) {
        int t = idx >> 7, d = idx & 127;
        int l = l0 + t;
        float acc = 0.f;
        #pragma unroll
        for (int j = 0; j < 4; j++) {
            int ls = l - 3 + j;
            float v = (ls >= 0) ? xiz[ls * 256 + d] : 0.f;
            acc = fmaf(scw[d * 4 + j], v, acc);
        }
        acc = fmaxf(acc, 0.f);
        sxc[t * 128 + d] = acc;
        xc[l * 128 + d] = acc;
    }
    __syncthreads();

    for (int idx = tid; idx < 64 * NXP; idx += 256) {
        int t = idx / NXP, n = idx % NXP;
        float acc = 0.f;
        #pragma unroll 8
        for (int dd = 0; dd < 128; dd++) acc = fmaf(sxc[t * 128 + dd], sWx[dd * NXP + n], acc);
        sdbl[t * NXP + n] = acc;
        if (n >= 4) bcout[(l0 + t) * 32 + (n - 4)] = acc;
    }
    __syncthreads();

    for (int idx = tid; idx < 8192; idx += 256) {
        int t = idx >> 7, d = idx & 127;
        float acc = bias[d];
        #pragma unroll
        for (int r = 0; r < 4; r++) acc = fmaf(sdbl[t * NXP + r], sWdt[r * 128 + d], acc);
        float sp = (acc > 20.f) ? acc : log1pf(__expf(acc));
        delta[(l0 + t) * 128 + d] = sp;
    }
}

// ============================================================
// Scan helpers
// ============================================================
__device__ __forceinline__ void compute_dA(float dl, float A0, const float* A,
                                           bool fast, float (&dA)[DS])
{
    if (fast) {
        float r = __expf(dl * A0);
        float r2 = r * r, r4 = r2 * r2, r8 = r4 * r4;
        dA[0] = r;        dA[1] = r2;       dA[2] = r2 * r;     dA[3] = r4;
        dA[4] = r4 * r;   dA[5] = r4 * r2;  dA[6] = r4 * dA[2]; dA[7] = r8;
        dA[8] = r8 * r;   dA[9] = r8 * r2;  dA[10] = r8 * dA[2]; dA[11] = r8 * r4;
        dA[12] = r8 * dA[4]; dA[13] = r8 * dA[5]; dA[14] = r8 * dA[6]; dA[15] = r8 * r8;
    } else {
        #pragma unroll
        for (int s = 0; s < DS; s++) dA[s] = __expf(dl * A[s]);
    }
}

__device__ __forceinline__ bool load_A(const float* __restrict__ Alog, int d,
                                       float (&A)[DS], float& A0)
{
    #pragma unroll
    for (int s = 0; s < DS; s++) A[s] = -__expf(Alog[d * DS + s]);
    A0 = A[0];
    bool fast = (A0 < 0.f);
    #pragma unroll
    for (int s = 0; s < DS; s++) {
        float t = (float)(s + 1) * A0;
        fast = fast && (fabsf(A[s] - t) <= 1e-3f * fabsf(t));
    }
    return fast;
}

// K: per-chunk local scan -> chunk product P (=exp(sumdl*A)), chunk sum S
__global__ void k_scan1(const float* __restrict__ delta, const float* __restrict__ u,
                        const float* __restrict__ bc, const float* __restrict__ Alog,
                        float* __restrict__ Pg, float* __restrict__ Sg)
{
    __shared__ float sD[LC * DI], sU[LC * DI], sB[LC * DS];
    int c = blockIdx.x, d = threadIdx.x;
    int l0 = c * LC;
    const float4* gD = (const float4*)(delta + l0 * DI);
    const float4* gU = (const float4*)(u + l0 * DI);
    #pragma unroll
    for (int k = 0; k < LC * DI / 4 / 128; k++) {
        ((float4*)sD)[d + k * 128] = gD[d + k * 128];
        ((float4*)sU)[d + k * 128] = gU[d + k * 128];
    }
    for (int idx = d; idx < LC * DS; idx += 128) {
        int t = idx >> 4, s = idx & 15;
        sB[idx] = bc[(l0 + t) * 32 + s];
    }
    __syncthreads();

    float A[DS], A0;
    bool fast = load_A(Alog, d, A, A0);

    float S[DS];
    #pragma unroll
    for (int s = 0; s < DS; s++) S[s] = 0.f;
    float sumdl = 0.f;

    #pragma unroll 4
    for (int t = 0; t < LC; t++) {
        float dl = sD[t * DI + d];
        float du = dl * sU[t * DI + d];
        sumdl += dl;
        float dA[DS];
        compute_dA(dl, A0, A, fast, dA);
        #pragma unroll
        for (int s = 0; s < DS; s++)
            S[s] = fmaf(dA[s], S[s], du * sB[t * DS + s]);
    }
    float P[DS];
    compute_dA(sumdl, A0, A, fast, P);
    int base = (c * DI + d) * DS;
    #pragma unroll
    for (int s = 0; s < DS; s++) { Pg[base + s] = P[s]; Sg[base + s] = S[s]; }
}

// Carry level 1: compose GRP chunks per group -> group aggregates
__global__ void k_carry1(const float* __restrict__ Pg, const float* __restrict__ Sg,
                         float* __restrict__ Pa, float* __restrict__ Sa)
{
    int idx = blockIdx.x * blockDim.x + threadIdx.x;   // 0 .. NGRP*NSEQ-1
    int g = idx / NSEQ, i = idx % NSEQ;
    float P = 1.f, S = 0.f;
    #pragma unroll 4
    for (int t = 0; t < GRP; t++) {
        int o = (g * GRP + t) * NSEQ + i;
        float p = Pg[o], s = Sg[o];
        S = fmaf(p, S, s);
        P *= p;
    }
    Pa[g * NSEQ + i] = P;
    Sa[g * NSEQ + i] = S;
}

// Carry level 2: serial scan over NGRP group aggregates -> group-start H (G)
__global__ void k_carry2(const float* __restrict__ Pa, const float* __restrict__ Sa,
                         float* __restrict__ G)
{
    int i = blockIdx.x * blockDim.x + threadIdx.x;     // 0 .. NSEQ-1
    float H = 0.f;
    for (int g = 0; g < NGRP; g++) {
        G[g * NSEQ + i] = H;
        H = fmaf(Pa[g * NSEQ + i], H, Sa[g * NSEQ + i]);
    }
}

// Carry level 3: expand group-start H to per-chunk H0
__global__ void k_carry3(const float* __restrict__ Pg, const float* __restrict__ Sg,
                         const float* __restrict__ G, float* __restrict__ H0)
{
    int idx = blockIdx.x * blockDim.x + threadIdx.x;
    int g = idx / NSEQ, i = idx % NSEQ;
    float H = G[g * NSEQ + i];
    #pragma unroll 4
    for (int t = 0; t < GRP; t++) {
        int o = (g * GRP + t) * NSEQ + i;
        H0[o] = H;
        H = fmaf(Pg[o], H, Sg[o]);
    }
}

// rescan with carry, emit yz = (y + u*D) * silu(z)
__global__ void k_scan2(const float* __restrict__ delta, const float* __restrict__ u,
                        const float* __restrict__ bc, const float* __restrict__ Alog,
                        const float* __restrict__ H0, const float* __restrict__ Dp,
                        const float* __restrict__ xiz, float* __restrict__ yz)
{
    __shared__ float sD[LC * DI], sU[LC * DI], sB[LC * DS], sC[LC * DS];
    int c = blockIdx.x, d = threadIdx.x;
    int l0 = c * LC;
    const float4* gD = (const float4*)(delta + l0 * DI);
    const float4* gU = (const float4*)(u + l0 * DI);
    #pragma unroll
    for (int k = 0; k < LC * DI / 4 / 128; k++) {
        ((float4*)sD)[d + k * 128] = gD[d + k * 128];
        ((float4*)sU)[d + k * 128] = gU[d + k * 128];
    }
    for (int idx = d; idx < LC * DS; idx += 128) {
        int t = idx >> 4, s = idx & 15;
        sB[idx] = bc[(l0 + t) * 32 + s];
        sC[idx] = bc[(l0 + t) * 32 + 16 + s];
    }
    __syncthreads();

    float A[DS], A0;
    bool fast = load_A(Alog, d, A, A0);

    float h[DS];
    #pragma unroll
    for (int s = 0; s < DS; s++) h[s] = H0[(c * DI + d) * DS + s];
    float Dd = Dp[d];

    #pragma unroll 2
    for (int t = 0; t < LC; t++) {
        float z = xiz[(l0 + t) * 256 + 128 + d];
        float dl = sD[t * DI + d];
        float uu = sU[t * DI + d];
        float du = dl * uu;
        float dA[DS];
        compute_dA(dl, A0, A, fast, dA);
        float y = 0.f;
        #pragma unroll
        for (int s = 0; s < DS; s++) {
            h[s] = fmaf(dA[s], h[s], du * sB[t * DS + s]);
            y = fmaf(h[s], sC[t * DS + s], y);
        }
        y = fmaf(uu, Dd, y);
        float sig = 1.f / (1.f + __expf(-z));
        yz[(l0 + t) * DI + d] = y * (z * sig);
    }
}

// ============================================================
// launch
// ============================================================
#define SM_G1 ((64 * 256 + 64 * 64 + 64 * 65) * 4)     // 98560
#define SM_F1 ((64 * 256 + 64 * 64) * 4)               // 81920
#define SM_G2 ((128 * 64 + 64 * 128 + 64 * 65) * 4)    // 82176
#define SM_CONV ((8192 + 4608 + 2304 + 512 + 512) * 4) // 64512

extern "C" void kernel_launch(void* const* d_in, const int* in_sizes, int n_in,
                              void* d_out, int out_size)
{
    const float* x    = (const float*)d_in[0];
    const float* ln1w = (const float*)d_in[1];
    const float* ln1b = (const float*)d_in[2];
    const float* Win  = (const float*)d_in[3];
    const float* cw   = (const float*)d_in[4];
    const float* Wxp  = (const float*)d_in[5];
    const float* Wdt  = (const float*)d_in[6];
    const float* dtb  = (const float*)d_in[7];
    const float* Alog = (const float*)d_in[8];
    const float* Dssm = (const float*)d_in[9];
    const float* Wout = (const float*)d_in[10];
    const float* ln2w = (const float*)d_in[11];
    const float* ln2b = (const float*)d_in[12];
    const float* Wf1  = (const float*)d_in[13];
    const float* Wf2  = (const float*)d_in[14];
    float* out = (float*)d_out;

    float* sc = nullptr;
    cudaGetSymbolAddress((void**)&sc, g_scratch);

    float* xiz   = sc + OFF_XIZ;
    float* xc    = sc + OFF_XC;
    float* delta = sc + OFF_DELTA;
    float* bcb   = sc + OFF_BC;
    float* Pg    = sc + OFF_P;
    float* Sg    = sc + OFF_S;
    float* H0    = sc + OFF_H0;
    float* Pa    = sc + OFF_PA;
    float* Sa    = sc + OFF_SA;
    float* Gb    = sc + OFF_G;
    float* yzb   = sc + OFF_YZ;
    float* xt2   = sc + OFF_XT2;
    float* hn    = sc + OFF_HN;
    float* gg    = sc + OFF_GG;

    cudaFuncSetAttribute(k_gemm<64, 256, 8, 0, 1, 0>, cudaFuncAttributeMaxDynamicSharedMemorySize, SM_G1);
    cudaFuncSetAttribute(k_gemm<64, 256, 8, 1, 0, 0>, cudaFuncAttributeMaxDynamicSharedMemorySize, SM_F1);
    cudaFuncSetAttribute(k_gemm<128, 64, 2, 2, 0, 1>, cudaFuncAttributeMaxDynamicSharedMemorySize, SM_G2);
    cudaFuncSetAttribute(k_gemm<128, 64, 2, 3, 0, 0>, cudaFuncAttributeMaxDynamicSharedMemorySize, SM_G2);
    cudaFuncSetAttribute(k_conv, cudaFuncAttributeMaxDynamicSharedMemorySize, SM_CONV);

    // 1. (LN1 fused) x -> xn @ W_in -> xi | z
    k_gemm<64, 256, 8, 0, 1, 0><<<296, 256, SM_G1>>>(x, Win, xiz, nullptr, ln1w, ln1b, nullptr);
    // 2. conv + relu + xproj + delta
    k_conv<<<NT, 256, SM_CONV>>>(xiz, cw, Wxp, Wdt, dtb, xc, delta, bcb);
    // 3. chunk-local scan
    k_scan1<<<NCH, 128>>>(delta, xc, bcb, Alog, Pg, Sg);
    // 4. hierarchical carry
    k_carry1<<<NGRP * NSEQ / 256, 256>>>(Pg, Sg, Pa, Sa);
    k_carry2<<<NSEQ / 256, 256>>>(Pa, Sa, Gb);
    k_carry3<<<NGRP * NSEQ / 256, 256>>>(Pg, Sg, Gb, H0);
    // 5. rescan + gate
    k_scan2<<<NCH, 128>>>(delta, xc, bcb, Alog, H0, Dssm, xiz, yzb);
    // 6. yz @ W_out + residual(x, transposed) -> xt2, LN2 -> hn
    k_gemm<128, 64, 2, 2, 0, 1><<<296, 256, SM_G2>>>(yzb, Wout, xt2, x, ln2w, ln2b, hn);
    // 7. hn @ W_ffn1, gated silu -> gg
    k_gemm<64, 256, 8, 1, 0, 0><<<296, 256, SM_F1>>>(hn, Wf1, gg, nullptr, nullptr, nullptr, nullptr);
    // 8. gg @ W_ffn2 + residual(xt2), transposed store -> out
    k_gemm<128, 64, 2, 3, 0, 0><<<296, 256, SM_G2>>>(gg, Wf2, out, xt2, nullptr, nullptr, nullptr);
}

// round 5
// speedup vs baseline: 1.0920x; 1.0920x over previous
#include <cuda_runtime.h>
#include <math.h>

typedef unsigned long long u64;

#define LTOK 31744          // 31*32*32
#define DI   128
#define DS   16
#define NXP  36             // DT_RANK + 2*DS
#define LC   32             // scan chunk length
#define NCH  (LTOK/LC)      // 992
#define NT   (LTOK/64)      // 496 token tiles of 64
#define NSEQ (DI*DS)        // 2048
#define GRP  32             // chunks per carry group
#define NGRP (NCH/GRP)      // 31

// ---- scratch layout (floats) ----
#define L64  (LTOK*64)
#define L128 (LTOK*128)
#define L256 (LTOK*256)
#define L32  (LTOK*32)
#define PSZ  (NCH*NSEQ)
#define GSZ  (NGRP*NSEQ)

#define OFF_XIZ   0
#define OFF_XC    (OFF_XIZ + L256)
#define OFF_DELTA (OFF_XC + L128)
#define OFF_BC    (OFF_DELTA + L128)
#define OFF_P     (OFF_BC + L32)
#define OFF_S     (OFF_P + PSZ)
#define OFF_H0    (OFF_S + PSZ)
#define OFF_PA    (OFF_H0 + PSZ)
#define OFF_SA    (OFF_PA + GSZ)
#define OFF_G     (OFF_SA + GSZ)
#define OFF_YZ    (OFF_G + GSZ)
#define OFF_XT2   (OFF_YZ + L128)
#define OFF_HN    (OFF_XT2 + L64)
#define OFF_GG    (OFF_HN + L64)
#define SCRATCH_TOTAL (OFF_GG + L128)

__device__ __align__(16) float g_scratch[SCRATCH_TOTAL];

// ---- packed f32x2 helpers (FFMA2 path: only reachable via PTX) ----
__device__ __forceinline__ u64 pk2(float lo, float hi) {
    u64 r; asm("mov.b64 %0, {%1,%2};" : "=l"(r) : "f"(lo), "f"(hi)); return r;
}
__device__ __forceinline__ void upk2(u64 v, float& lo, float& hi) {
    asm("mov.b64 {%0,%1}, %2;" : "=f"(lo), "=f"(hi) : "l"(v));
}
__device__ __forceinline__ u64 ffma2(u64 a, u64 b, u64 c) {
    u64 d; asm("fma.rn.f32x2 %0, %1, %2, %3;" : "=l"(d) : "l"(a), "l"(b), "l"(c)); return d;
}
__device__ __forceinline__ u64 fmul2(u64 a, u64 b) {
    u64 d; asm("mul.rn.f32x2 %0, %1, %2;" : "=l"(d) : "l"(a), "l"(b)); return d;
}

// ============================================================
// Persistent register-tiled GEMM (packed f32x2 mainloop):
//   Y[L,N] = X[L,K] @ W[K,N]
// Thread (tx,ty): rows ty*8+i, column PAIRS {2tx+64j, 2tx+64j+1}, j<RP=N/64.
// LNIN=1: X is raw x in [C=64, L] layout; tile transposed+LayerNormed.
// EPI 0: plain store
// EPI 1: gated FFN1: Y[l,c] = silu(o[l,c]) * o[l,c+128]
// EPI 2: out-proj: v = acc + residual; Y=v; Y2=LN(v)*lw+lb (RTR: R in [C,L])
// EPI 3: final: v = acc + R([L,64]); Y[c*L + l] = v
// ============================================================
template<int K, int N, int RP, int EPI, int LNIN, int RTR>
__global__ void __launch_bounds__(256, 2)
k_gemm(const float* __restrict__ X, const float* __restrict__ W,
       float* __restrict__ Y, const float* __restrict__ R,
       const float* __restrict__ lw, const float* __restrict__ lb,
       float* __restrict__ Y2)
{
    extern __shared__ __align__(16) float sm[];
    float* sW  = sm;                    // K*N
    float* sX  = sm + K * N;            // 64*K  (reused as sT 64x65 in EPI 2/3)
    float* sAux = sm + K * N + 64 * K;  // 64*65
    int tid = threadIdx.x, tx = tid & 31, ty = tid >> 5;

    for (int i = tid; i < K * N; i += 256) sW[i] = W[i];
    __syncthreads();

    for (int tile = blockIdx.x; tile < NT; tile += gridDim.x) {
        int l0 = tile * 64;

        if (LNIN) {
            for (int idx = tid; idx < 4096; idx += 256) {
                int c = idx >> 6, i = idx & 63;
                sAux[i * 65 + c] = X[c * LTOK + l0 + i];
            }
            __syncthreads();
            int r = tid >> 2, q = tid & 3;
            float s = 0.f, ss = 0.f;
            #pragma unroll
            for (int c = q * 16; c < q * 16 + 16; c++) {
                float v = sAux[r * 65 + c]; s += v; ss += v * v;
            }
            s  += __shfl_xor_sync(~0u, s, 1);  ss += __shfl_xor_sync(~0u, ss, 1);
            s  += __shfl_xor_sync(~0u, s, 2);  ss += __shfl_xor_sync(~0u, ss, 2);
            float mu = s * (1.f / 64.f);
            float rs = rsqrtf(ss * (1.f / 64.f) - mu * mu + 1e-5f);
            #pragma unroll
            for (int c = q * 16; c < q * 16 + 16; c++)
                sX[r * 64 + c] = (sAux[r * 65 + c] - mu) * rs * lw[c] + lb[c];
        } else {
            for (int i = tid; i < 64 * K; i += 256) sX[i] = X[l0 * K + i];
        }
        if (EPI >= 2) {
            if (RTR) {
                for (int idx = tid; idx < 4096; idx += 256) {
                    int c = idx >> 6, i = idx & 63;
                    sAux[i * 65 + c] = R[c * LTOK + l0 + i];
                }
            } else {
                for (int idx = tid; idx < 4096; idx += 256) {
                    int r = idx >> 6, c = idx & 63;
                    sAux[r * 65 + c] = R[(l0 + r) * 64 + c];
                }
            }
        }
        __syncthreads();

        u64 accp[8][RP];
        #pragma unroll
        for (int i = 0; i < 8; i++)
            #pragma unroll
            for (int j = 0; j < RP; j++) accp[i][j] = 0ULL;

        #pragma unroll 4
        for (int k2 = 0; k2 < K; k2 += 2) {
            float2 xv[8];
            #pragma unroll
            for (int i = 0; i < 8; i++)
                xv[i] = *reinterpret_cast<const float2*>(&sX[(ty * 8 + i) * K + k2]);
            #pragma unroll
            for (int kk = 0; kk < 2; kk++) {
                u64 wv[RP];
                #pragma unroll
                for (int j = 0; j < RP; j++)
                    wv[j] = *reinterpret_cast<const u64*>(&sW[(k2 + kk) * N + 2 * tx + 64 * j]);
                #pragma unroll
                for (int i = 0; i < 8; i++) {
                    float xs = kk ? xv[i].y : xv[i].x;
                    u64 xp = pk2(xs, xs);
                    #pragma unroll
                    for (int j = 0; j < RP; j++) accp[i][j] = ffma2(xp, wv[j], accp[i][j]);
                }
            }
        }
        __syncthreads();

        if (EPI == 0) {
            #pragma unroll
            for (int i = 0; i < 8; i++)
                #pragma unroll
                for (int j = 0; j < RP; j++)
                    *reinterpret_cast<u64*>(&Y[(l0 + ty * 8 + i) * N + 2 * tx + 64 * j]) = accp[i][j];
        } else if (EPI == 1) {
            #pragma unroll
            for (int i = 0; i < 8; i++)
                #pragma unroll
                for (int j = 0; j < 2; j++) {
                    float g0, g1, v0, v1;
                    upk2(accp[i][j], g0, g1);
                    upk2(accp[i][j + 2], v0, v1);
                    float r0 = g0 / (1.f + __expf(-g0)) * v0;
                    float r1 = g1 / (1.f + __expf(-g1)) * v1;
                    *reinterpret_cast<u64*>(&Y[(l0 + ty * 8 + i) * 128 + 2 * tx + 64 * j]) = pk2(r0, r1);
                }
        } else {
            float* sT = sX;
            #pragma unroll
            for (int i = 0; i < 8; i++) {
                int row = ty * 8 + i, col = 2 * tx;
                float a0, a1;
                upk2(accp[i][0], a0, a1);
                sT[row * 65 + col]     = a0 + sAux[row * 65 + col];
                sT[row * 65 + col + 1] = a1 + sAux[row * 65 + col + 1];
            }
            __syncthreads();
            if (EPI == 2) {
                int r = tid >> 2, q = tid & 3;
                float s = 0.f, ss = 0.f;
                #pragma unroll
                for (int c = q * 16; c < q * 16 + 16; c++) {
                    float v = sT[r * 65 + c]; s += v; ss += v * v;
                }
                s  += __shfl_xor_sync(~0u, s, 1);  ss += __shfl_xor_sync(~0u, ss, 1);
                s  += __shfl_xor_sync(~0u, s, 2);  ss += __shfl_xor_sync(~0u, ss, 2);
                float mu = s * (1.f / 64.f);
                float rs = rsqrtf(ss * (1.f / 64.f) - mu * mu + 1e-5f);
                #pragma unroll
                for (int c = q * 16; c < q * 16 + 16; c++) {
                    float v = sT[r * 65 + c];
                    Y[(l0 + r) * 64 + c]  = v;
                    Y2[(l0 + r) * 64 + c] = (v - mu) * rs * lw[c] + lb[c];
                }
            } else {
                for (int idx = tid; idx < 4096; idx += 256) {
                    int ll = idx & 63, c = idx >> 6;
                    Y[c * LTOK + l0 + ll] = sT[ll * 65 + c];
                }
            }
            __syncthreads();
        }
    }
}

// ============================================================
// conv + relu + xproj (packed) + softplus(delta) (packed)
// ============================================================
__global__ void k_conv(const float* __restrict__ xiz, const float* __restrict__ cw,
                       const float* __restrict__ Wxp, const float* __restrict__ Wdt,
                       const float* __restrict__ bias,
                       float* __restrict__ xc, float* __restrict__ delta,
                       float* __restrict__ bcout)
{
    extern __shared__ __align__(16) float sm[];
    float* sxc  = sm;               // 64*128
    float* sWx  = sxc + 8192;       // 128*36
    float* sdbl = sWx + 4608;       // 64*36
    float* sWdt = sdbl + 2304;      // 4*128
    float* scw  = sWdt + 512;       // 512
    int tid = threadIdx.x;
    int l0 = blockIdx.x * 64;

    for (int i = tid; i < 4608; i += 256) sWx[i] = Wxp[i];
    for (int i = tid; i < 512; i += 256) { sWdt[i] = Wdt[i]; scw[i] = cw[i]; }
    __syncthreads();

    for (int idx = tid; idx < 8192; idx += 256) {
        int t = idx >> 7, d = idx & 127;
        int l = l0 + t;
        float acc = 0.f;
        #pragma unroll
        for (int j = 0; j < 4; j++) {
            int ls = l - 3 + j;
            float v = (ls >= 0) ? xiz[ls * 256 + d] : 0.f;
            acc = fmaf(scw[d * 4 + j], v, acc);
        }
        acc = fmaxf(acc, 0.f);
        sxc[t * 128 + d] = acc;
        xc[l * 128 + d] = acc;
    }
    __syncthreads();

    // xproj: 64 tokens x 18 column-pairs, K=128, packed FMA
    for (int idx = tid; idx < 64 * 18; idx += 256) {
        int t = idx / 18, j = idx % 18;
        u64 acc = 0ULL;
        #pragma unroll 8
        for (int dd = 0; dd < 128; dd++) {
            u64 w = *reinterpret_cast<const u64*>(&sWx[dd * NXP + 2 * j]);
            float xs = sxc[t * 128 + dd];
            acc = ffma2(pk2(xs, xs), w, acc);
        }
        *reinterpret_cast<u64*>(&sdbl[t * NXP + 2 * j]) = acc;
        if (j >= 2)
            *reinterpret_cast<u64*>(&bcout[(l0 + t) * 32 + 2 * j - 4]) = acc;
    }
    __syncthreads();

    // delta: 64 tokens x 64 d-pairs, packed
    for (int idx = tid; idx < 4096; idx += 256) {
        int t = idx >> 6, dp = idx & 63;
        u64 acc = *reinterpret_cast<const u64*>(&bias[2 * dp]);
        #pragma unroll
        for (int r = 0; r < 4; r++) {
            float xs = sdbl[t * NXP + r];
            u64 w = *reinterpret_cast<const u64*>(&sWdt[r * 128 + 2 * dp]);
            acc = ffma2(pk2(xs, xs), w, acc);
        }
        float a0, a1;
        upk2(acc, a0, a1);
        float sp0 = (a0 > 20.f) ? a0 : log1pf(__expf(a0));
        float sp1 = (a1 > 20.f) ? a1 : log1pf(__expf(a1));
        *reinterpret_cast<u64*>(&delta[(l0 + t) * 128 + 2 * dp]) = pk2(sp0, sp1);
    }
}

// ============================================================
// Scan helpers (packed): dA pairs {r^(2k+1), r^(2k+2)} via r^2 ladder
// ============================================================
__device__ __forceinline__ void compute_dAp(float dl, float A0, const float* A,
                                            bool fast, u64 (&dAp)[8])
{
    if (fast) {
        float r = __expf(dl * A0), r2 = r * r;
        u64 r2p = pk2(r2, r2);
        dAp[0] = pk2(r, r2);
        #pragma unroll
        for (int k = 1; k < 8; k++) dAp[k] = fmul2(dAp[k - 1], r2p);
    } else {
        #pragma unroll
        for (int k = 0; k < 8; k++)
            dAp[k] = pk2(__expf(dl * A[2 * k]), __expf(dl * A[2 * k + 1]));
    }
}

__device__ __forceinline__ bool load_A(const float* __restrict__ Alog, int d,
                                       float (&A)[DS], float& A0)
{
    #pragma unroll
    for (int s = 0; s < DS; s++) A[s] = -__expf(Alog[d * DS + s]);
    A0 = A[0];
    bool fast = (A0 < 0.f);
    #pragma unroll
    for (int s = 0; s < DS; s++) {
        float t = (float)(s + 1) * A0;
        fast = fast && (fabsf(A[s] - t) <= 1e-3f * fabsf(t));
    }
    return fast;
}

// per-chunk local scan -> chunk product P (=exp(sumdl*A)), chunk sum S
__global__ void k_scan1(const float* __restrict__ delta, const float* __restrict__ u,
                        const float* __restrict__ bc, const float* __restrict__ Alog,
                        float* __restrict__ Pg, float* __restrict__ Sg)
{
    __shared__ __align__(16) float sD[LC * DI], sU[LC * DI], sB[LC * DS];
    int c = blockIdx.x, d = threadIdx.x;
    int l0 = c * LC;
    const float4* gD = (const float4*)(delta + l0 * DI);
    const float4* gU = (const float4*)(u + l0 * DI);
    #pragma unroll
    for (int k = 0; k < LC * DI / 4 / 128; k++) {
        ((float4*)sD)[d + k * 128] = gD[d + k * 128];
        ((float4*)sU)[d + k * 128] = gU[d + k * 128];
    }
    for (int idx = d; idx < LC * DS; idx += 128) {
        int t = idx >> 4, s = idx & 15;
        sB[idx] = bc[(l0 + t) * 32 + s];
    }
    __syncthreads();

    float A[DS], A0;
    bool fast = load_A(Alog, d, A, A0);

    u64 Sp[8];
    #pragma unroll
    for (int k = 0; k < 8; k++) Sp[k] = 0ULL;
    float sumdl = 0.f;

    #pragma unroll 4
    for (int t = 0; t < LC; t++) {
        float dl = sD[t * DI + d];
        float du = dl * sU[t * DI + d];
        sumdl += dl;
        u64 dAp[8];
        compute_dAp(dl, A0, A, fast, dAp);
        u64 dup = pk2(du, du);
        #pragma unroll
        for (int k = 0; k < 8; k++) {
            u64 Bp = *reinterpret_cast<const u64*>(&sB[t * DS + 2 * k]);
            Sp[k] = ffma2(dAp[k], Sp[k], fmul2(dup, Bp));
        }
    }
    u64 Pp[8];
    compute_dAp(sumdl, A0, A, fast, Pp);
    int base = (c * DI + d) * DS;
    #pragma unroll
    for (int k = 0; k < 8; k++) {
        *reinterpret_cast<u64*>(&Pg[base + 2 * k]) = Pp[k];
        *reinterpret_cast<u64*>(&Sg[base + 2 * k]) = Sp[k];
    }
}

// Carry level 1: compose GRP chunks per group -> group aggregates
__global__ void k_carry1(const float* __restrict__ Pg, const float* __restrict__ Sg,
                         float* __restrict__ Pa, float* __restrict__ Sa)
{
    int idx = blockIdx.x * blockDim.x + threadIdx.x;
    int g = idx / NSEQ, i = idx % NSEQ;
    float P = 1.f, S = 0.f;
    #pragma unroll 4
    for (int t = 0; t < GRP; t++) {
        int o = (g * GRP + t) * NSEQ + i;
        float p = Pg[o], s = Sg[o];
        S = fmaf(p, S, s);
        P *= p;
    }
    Pa[g * NSEQ + i] = P;
    Sa[g * NSEQ + i] = S;
}

// Carry level 2: serial scan over NGRP group aggregates
__global__ void k_carry2(const float* __restrict__ Pa, const float* __restrict__ Sa,
                         float* __restrict__ G)
{
    int i = blockIdx.x * blockDim.x + threadIdx.x;
    float H = 0.f;
    for (int g = 0; g < NGRP; g++) {
        G[g * NSEQ + i] = H;
        H = fmaf(Pa[g * NSEQ + i], H, Sa[g * NSEQ + i]);
    }
}

// Carry level 3: expand group-start H to per-chunk H0
__global__ void k_carry3(const float* __restrict__ Pg, const float* __restrict__ Sg,
                         const float* __restrict__ G, float* __restrict__ H0)
{
    int idx = blockIdx.x * blockDim.x + threadIdx.x;
    int g = idx / NSEQ, i = idx % NSEQ;
    float H = G[g * NSEQ + i];
    #pragma unroll 4
    for (int t = 0; t < GRP; t++) {
        int o = (g * GRP + t) * NSEQ + i;
        H0[o] = H;
        H = fmaf(Pg[o], H, Sg[o]);
    }
}

// rescan with carry, emit yz = (y + u*D) * silu(z)  (packed state)
__global__ void k_scan2(const float* __restrict__ delta, const float* __restrict__ u,
                        const float* __restrict__ bc, const float* __restrict__ Alog,
                        const float* __restrict__ H0, const float* __restrict__ Dp,
                        const float* __restrict__ xiz, float* __restrict__ yz)
{
    __shared__ __align__(16) float sD[LC * DI], sU[LC * DI], sB[LC * DS], sC[LC * DS];
    int c = blockIdx.x, d = threadIdx.x;
    int l0 = c * LC;
    const float4* gD = (const float4*)(delta + l0 * DI);
    const float4* gU = (const float4*)(u + l0 * DI);
    #pragma unroll
    for (int k = 0; k < LC * DI / 4 / 128; k++) {
        ((float4*)sD)[d + k * 128] = gD[d + k * 128];
        ((float4*)sU)[d + k * 128] = gU[d + k * 128];
    }
    for (int idx = d; idx < LC * DS; idx += 128) {
        int t = idx >> 4, s = idx & 15;
        sB[idx] = bc[(l0 + t) * 32 + s];
        sC[idx] = bc[(l0 + t) * 32 + 16 + s];
    }
    __syncthreads();

    float A[DS], A0;
    bool fast = load_A(Alog, d, A, A0);

    u64 hp[8];
    #pragma unroll
    for (int k = 0; k < 8; k++)
        hp[k] = *reinterpret_cast<const u64*>(&H0[(c * DI + d) * DS + 2 * k]);
    float Dd = Dp[d];

    #pragma unroll 2
    for (int t = 0; t < LC; t++) {
        float z = xiz[(l0 + t) * 256 + 128 + d];
        float dl = sD[t * DI + d];
        float uu = sU[t * DI + d];
        float du = dl * uu;
        u64 dAp[8];
        compute_dAp(dl, A0, A, fast, dAp);
        u64 dup = pk2(du, du);
        u64 yp0 = 0ULL, yp1 = 0ULL;
        #pragma unroll
        for (int k = 0; k < 8; k++) {
            u64 Bp = *reinterpret_cast<const u64*>(&sB[t * DS + 2 * k]);
            u64 Cp = *reinterpret_cast<const u64*>(&sC[t * DS + 2 * k]);
            hp[k] = ffma2(dAp[k], hp[k], fmul2(dup, Bp));
            if (k & 1) yp1 = ffma2(hp[k], Cp, yp1);
            else       yp0 = ffma2(hp[k], Cp, yp0);
        }
        float y0, y1, y2, y3;
        upk2(yp0, y0, y1);
        upk2(yp1, y2, y3);
        float y = (y0 + y1) + (y2 + y3);
        y = fmaf(uu, Dd, y);
        float sig = 1.f / (1.f + __expf(-z));
        yz[(l0 + t) * DI + d] = y * (z * sig);
    }
}

// ============================================================
// launch
// ============================================================
#define SM_G1 ((64 * 256 + 64 * 64 + 64 * 65) * 4)     // 98560
#define SM_F1 ((64 * 256 + 64 * 64) * 4)               // 81920
#define SM_G2 ((128 * 64 + 64 * 128 + 64 * 65) * 4)    // 82176
#define SM_CONV ((8192 + 4608 + 2304 + 512 + 512) * 4) // 64512

extern "C" void kernel_launch(void* const* d_in, const int* in_sizes, int n_in,
                              void* d_out, int out_size)
{
    const float* x    = (const float*)d_in[0];
    const float* ln1w = (const float*)d_in[1];
    const float* ln1b = (const float*)d_in[2];
    const float* Win  = (const float*)d_in[3];
    const float* cw   = (const float*)d_in[4];
    const float* Wxp  = (const float*)d_in[5];
    const float* Wdt  = (const float*)d_in[6];
    const float* dtb  = (const float*)d_in[7];
    const float* Alog = (const float*)d_in[8];
    const float* Dssm = (const float*)d_in[9];
    const float* Wout = (const float*)d_in[10];
    const float* ln2w = (const float*)d_in[11];
    const float* ln2b = (const float*)d_in[12];
    const float* Wf1  = (const float*)d_in[13];
    const float* Wf2  = (const float*)d_in[14];
    float* out = (float*)d_out;

    float* sc = nullptr;
    cudaGetSymbolAddress((void**)&sc, g_scratch);

    float* xiz   = sc + OFF_XIZ;
    float* xc    = sc + OFF_XC;
    float* delta = sc + OFF_DELTA;
    float* bcb   = sc + OFF_BC;
    float* Pg    = sc + OFF_P;
    float* Sg    = sc + OFF_S;
    float* H0    = sc + OFF_H0;
    float* Pa    = sc + OFF_PA;
    float* Sa    = sc + OFF_SA;
    float* Gb    = sc + OFF_G;
    float* yzb   = sc + OFF_YZ;
    float* xt2   = sc + OFF_XT2;
    float* hn    = sc + OFF_HN;
    float* gg    = sc + OFF_GG;

    cudaFuncSetAttribute(k_gemm<64, 256, 4, 0, 1, 0>, cudaFuncAttributeMaxDynamicSharedMemorySize, SM_G1);
    cudaFuncSetAttribute(k_gemm<64, 256, 4, 1, 0, 0>, cudaFuncAttributeMaxDynamicSharedMemorySize, SM_F1);
    cudaFuncSetAttribute(k_gemm<128, 64, 1, 2, 0, 1>, cudaFuncAttributeMaxDynamicSharedMemorySize, SM_G2);
    cudaFuncSetAttribute(k_gemm<128, 64, 1, 3, 0, 0>, cudaFuncAttributeMaxDynamicSharedMemorySize, SM_G2);
    cudaFuncSetAttribute(k_conv, cudaFuncAttributeMaxDynamicSharedMemorySize, SM_CONV);

    // 1. (LN1 fused) x -> xn @ W_in -> xi | z
    k_gemm<64, 256, 4, 0, 1, 0><<<296, 256, SM_G1>>>(x, Win, xiz, nullptr, ln1w, ln1b, nullptr);
    // 2. conv + relu + xproj + delta
    k_conv<<<NT, 256, SM_CONV>>>(xiz, cw, Wxp, Wdt, dtb, xc, delta, bcb);
    // 3. chunk-local scan
    k_scan1<<<NCH, 128>>>(delta, xc, bcb, Alog, Pg, Sg);
    // 4. hierarchical carry
    k_carry1<<<NGRP * NSEQ / 256, 256>>>(Pg, Sg, Pa, Sa);
    k_carry2<<<NSEQ / 256, 256>>>(Pa, Sa, Gb);
    k_carry3<<<NGRP * NSEQ / 256, 256>>>(Pg, Sg, Gb, H0);
    // 5. rescan + gate
    k_scan2<<<NCH, 128>>>(delta, xc, bcb, Alog, H0, Dssm, xiz, yzb);
    // 6. yz @ W_out + residual(x, transposed) -> xt2, LN2 -> hn
    k_gemm<128, 64, 1, 2, 0, 1><<<296, 256, SM_G2>>>(yzb, Wout, xt2, x, ln2w, ln2b, hn);
    // 7. hn @ W_ffn1, gated silu -> gg
    k_gemm<64, 256, 4, 1, 0, 0><<<296, 256, SM_F1>>>(hn, Wf1, gg, nullptr, nullptr, nullptr, nullptr);
    // 8. gg @ W_ffn2 + residual(xt2), transposed store -> out
    k_gemm<128, 64, 1, 3, 0, 0><<<296, 256, SM_G2>>>(gg, Wf2, out, xt2, nullptr, nullptr, nullptr);
}

// round 6
// speedup vs baseline: 1.1639x; 1.0658x over previous
#include <cuda_runtime.h>
#include <math.h>

typedef unsigned long long u64;

#define LTOK 31744          // 31*32*32
#define DI   128
#define DS   16
#define NXP  36             // DT_RANK + 2*DS
#define LC   32             // scan chunk length
#define NCH  (LTOK/LC)      // 992
#define NT   (LTOK/64)      // 496 token tiles of 64
#define NSEQ (DI*DS)        // 2048
#define GRP  32             // chunks per carry group
#define NGRP (NCH/GRP)      // 31

// ---- scratch layout (floats) ----
#define L64  (LTOK*64)
#define L128 (LTOK*128)
#define L256 (LTOK*256)
#define L32  (LTOK*32)
#define PSZ  (NCH*NSEQ)
#define GSZ  (NGRP*NSEQ)

#define OFF_XIZ   0
#define OFF_XC    (OFF_XIZ + L256)
#define OFF_DELTA (OFF_XC + L128)
#define OFF_BC    (OFF_DELTA + L128)
#define OFF_P     (OFF_BC + L32)
#define OFF_S     (OFF_P + PSZ)
#define OFF_H0    (OFF_S + PSZ)
#define OFF_PA    (OFF_H0 + PSZ)
#define OFF_SA    (OFF_PA + GSZ)
#define OFF_G     (OFF_SA + GSZ)
#define OFF_YZ    (OFF_G + GSZ)
#define SCRATCH_TOTAL (OFF_YZ + L128)

__device__ __align__(16) float g_scratch[SCRATCH_TOTAL];

// ---- packed f32x2 helpers (FFMA2 only reachable via PTX) ----
__device__ __forceinline__ u64 pk2(float lo, float hi) {
    u64 r; asm("mov.b64 %0, {%1,%2};" : "=l"(r) : "f"(lo), "f"(hi)); return r;
}
__device__ __forceinline__ void upk2(u64 v, float& lo, float& hi) {
    asm("mov.b64 {%0,%1}, %2;" : "=f"(lo), "=f"(hi) : "l"(v));
}
__device__ __forceinline__ u64 ffma2(u64 a, u64 b, u64 c) {
    u64 d; asm("fma.rn.f32x2 %0, %1, %2, %3;" : "=l"(d) : "l"(a), "l"(b), "l"(c)); return d;
}
__device__ __forceinline__ u64 fmul2(u64 a, u64 b) {
    u64 d; asm("mul.rn.f32x2 %0, %1, %2;" : "=l"(d) : "l"(a), "l"(b)); return d;
}

// ============================================================
// GEMM1 (persistent, packed): xiz = LN1(x^T) @ W_in   [L,256]
// X is raw x in [C=64, L] layout; tile transposed+LayerNormed in smem.
// ============================================================
__global__ void __launch_bounds__(256, 2)
k_gemm1(const float* __restrict__ X, const float* __restrict__ W,
        float* __restrict__ Y, const float* __restrict__ lw,
        const float* __restrict__ lb)
{
    extern __shared__ __align__(16) float sm[];
    float* sW  = sm;                 // 64*256
    float* sX  = sm + 64 * 256;      // 64*64
    float* sAux = sX + 64 * 64;      // 64*65
    int tid = threadIdx.x, tx = tid & 31, ty = tid >> 5;

    for (int i = tid; i < 64 * 256; i += 256) sW[i] = W[i];
    __syncthreads();

    for (int tile = blockIdx.x; tile < NT; tile += gridDim.x) {
        int l0 = tile * 64;
        for (int idx = tid; idx < 4096; idx += 256) {
            int c = idx >> 6, i = idx & 63;
            sAux[i * 65 + c] = X[c * LTOK + l0 + i];
        }
        __syncthreads();
        int r = tid >> 2, q = tid & 3;
        float s = 0.f, ss = 0.f;
        #pragma unroll
        for (int c = q * 16; c < q * 16 + 16; c++) {
            float v = sAux[r * 65 + c]; s += v; ss += v * v;
        }
        s  += __shfl_xor_sync(~0u, s, 1);  ss += __shfl_xor_sync(~0u, ss, 1);
        s  += __shfl_xor_sync(~0u, s, 2);  ss += __shfl_xor_sync(~0u, ss, 2);
        float mu = s * (1.f / 64.f);
        float rs = rsqrtf(ss * (1.f / 64.f) - mu * mu + 1e-5f);
        #pragma unroll
        for (int c = q * 16; c < q * 16 + 16; c++)
            sX[r * 64 + c] = (sAux[r * 65 + c] - mu) * rs * lw[c] + lb[c];
        __syncthreads();

        u64 accp[8][4];
        #pragma unroll
        for (int i = 0; i < 8; i++)
            #pragma unroll
            for (int j = 0; j < 4; j++) accp[i][j] = 0ULL;

        #pragma unroll 4
        for (int k2 = 0; k2 < 64; k2 += 2) {
            float2 xv[8];
            #pragma unroll
            for (int i = 0; i < 8; i++)
                xv[i] = *reinterpret_cast<const float2*>(&sX[(ty * 8 + i) * 64 + k2]);
            #pragma unroll
            for (int kk = 0; kk < 2; kk++) {
                u64 wv[4];
                #pragma unroll
                for (int j = 0; j < 4; j++)
                    wv[j] = *reinterpret_cast<const u64*>(&sW[(k2 + kk) * 256 + 2 * tx + 64 * j]);
                #pragma unroll
                for (int i = 0; i < 8; i++) {
                    float xs = kk ? xv[i].y : xv[i].x;
                    u64 xp = pk2(xs, xs);
                    #pragma unroll
                    for (int j = 0; j < 4; j++) accp[i][j] = ffma2(xp, wv[j], accp[i][j]);
                }
            }
        }
        __syncthreads();

        #pragma unroll
        for (int i = 0; i < 8; i++)
            #pragma unroll
            for (int j = 0; j < 4; j++)
                *reinterpret_cast<u64*>(&Y[(l0 + ty * 8 + i) * 256 + 2 * tx + 64 * j]) = accp[i][j];
    }
}

// ============================================================
// Scan helpers (packed): dA pairs {r^(2k+1), r^(2k+2)} via r^2 ladder
// ============================================================
__device__ __forceinline__ void compute_dAp(float dl, float A0, const float* A,
                                            bool fast, u64 (&dAp)[8])
{
    if (fast) {
        float r = __expf(dl * A0), r2 = r * r;
        u64 r2p = pk2(r2, r2);
        dAp[0] = pk2(r, r2);
        #pragma unroll
        for (int k = 1; k < 8; k++) dAp[k] = fmul2(dAp[k - 1], r2p);
    } else {
        #pragma unroll
        for (int k = 0; k < 8; k++)
            dAp[k] = pk2(__expf(dl * A[2 * k]), __expf(dl * A[2 * k + 1]));
    }
}

__device__ __forceinline__ bool load_A(const float* __restrict__ Alog, int d,
                                       float (&A)[DS], float& A0)
{
    #pragma unroll
    for (int s = 0; s < DS; s++) A[s] = -__expf(Alog[d * DS + s]);
    A0 = A[0];
    bool fast = (A0 < 0.f);
    #pragma unroll
    for (int s = 0; s < DS; s++) {
        float t = (float)(s + 1) * A0;
        fast = fast && (fabsf(A[s] - t) <= 1e-3f * fabsf(t));
    }
    return fast;
}

// ============================================================
// conv + relu + xproj + softplus(delta) + FUSED chunk-local scan1
// (block = 64 tokens = 2 chunks of LC=32)
// ============================================================
__global__ void k_conv2(const float* __restrict__ xiz, const float* __restrict__ cw,
                        const float* __restrict__ Wxp, const float* __restrict__ Wdt,
                        const float* __restrict__ bias, const float* __restrict__ Alog,
                        float* __restrict__ xc, float* __restrict__ delta,
                        float* __restrict__ bcout,
                        float* __restrict__ Pg, float* __restrict__ Sg)
{
    extern __shared__ __align__(16) float sm[];
    float* sxc  = sm;               // 64*128
    float* sdl  = sxc + 8192;       // 64*128
    float* sWx  = sdl + 8192;       // 128*36
    float* sdbl = sWx + 4608;       // 64*36
    float* sWdt = sdbl + 2304;      // 4*128
    float* scw  = sWdt + 512;       // 512
    int tid = threadIdx.x;
    int l0 = blockIdx.x * 64;

    for (int i = tid; i < 4608; i += 256) sWx[i] = Wxp[i];
    for (int i = tid; i < 512; i += 256) { sWdt[i] = Wdt[i]; scw[i] = cw[i]; }
    __syncthreads();

    for (int idx = tid; idx < 8192; idx += 256) {
        int t = idx >> 7, d = idx & 127;
        int l = l0 + t;
        float acc = 0.f;
        #pragma unroll
        for (int j = 0; j < 4; j++) {
            int ls = l - 3 + j;
            float v = (ls >= 0) ? xiz[ls * 256 + d] : 0.f;
            acc = fmaf(scw[d * 4 + j], v, acc);
        }
        acc = fmaxf(acc, 0.f);
        sxc[t * 128 + d] = acc;
        xc[l * 128 + d] = acc;
    }
    __syncthreads();

    // xproj: 64 tokens x 18 column-pairs, K=128, packed FMA
    for (int idx = tid; idx < 64 * 18; idx += 256) {
        int t = idx / 18, j = idx % 18;
        u64 acc = 0ULL;
        #pragma unroll 8
        for (int dd = 0; dd < 128; dd++) {
            u64 w = *reinterpret_cast<const u64*>(&sWx[dd * NXP + 2 * j]);
            float xs = sxc[t * 128 + dd];
            acc = ffma2(pk2(xs, xs), w, acc);
        }
        *reinterpret_cast<u64*>(&sdbl[t * NXP + 2 * j]) = acc;
        if (j >= 2)
            *reinterpret_cast<u64*>(&bcout[(l0 + t) * 32 + 2 * j - 4]) = acc;
    }
    __syncthreads();

    // delta: 64 tokens x 64 d-pairs, packed
    for (int idx = tid; idx < 4096; idx += 256) {
        int t = idx >> 6, dp = idx & 63;
        u64 acc = *reinterpret_cast<const u64*>(&bias[2 * dp]);
        #pragma unroll
        for (int r = 0; r < 4; r++) {
            float xs = sdbl[t * NXP + r];
            u64 w = *reinterpret_cast<const u64*>(&sWdt[r * 128 + 2 * dp]);
            acc = ffma2(pk2(xs, xs), w, acc);
        }
        float a0, a1;
        upk2(acc, a0, a1);
        float sp0 = (a0 > 20.f) ? a0 : log1pf(__expf(a0));
        float sp1 = (a1 > 20.f) ? a1 : log1pf(__expf(a1));
        u64 sp = pk2(sp0, sp1);
        *reinterpret_cast<u64*>(&sdl[t * 128 + 2 * dp]) = sp;
        *reinterpret_cast<u64*>(&delta[(l0 + t) * 128 + 2 * dp]) = sp;
    }
    __syncthreads();

    // ---- fused scan1: thread = (chunk in {0,1}, channel d) ----
    int ch = tid >> 7, d = tid & 127;
    int c = blockIdx.x * 2 + ch;
    int t0 = ch * LC;

    float A[DS], A0;
    bool fast = load_A(Alog, d, A, A0);

    u64 Sp[8];
    #pragma unroll
    for (int k = 0; k < 8; k++) Sp[k] = 0ULL;
    float sumdl = 0.f;

    #pragma unroll 4
    for (int t = 0; t < LC; t++) {
        float dl = sdl[(t0 + t) * 128 + d];
        float du = dl * sxc[(t0 + t) * 128 + d];
        sumdl += dl;
        u64 dAp[8];
        compute_dAp(dl, A0, A, fast, dAp);
        u64 dup = pk2(du, du);
        #pragma unroll
        for (int k = 0; k < 8; k++) {
            u64 Bp = *reinterpret_cast<const u64*>(&sdbl[(t0 + t) * NXP + 4 + 2 * k]);
            Sp[k] = ffma2(dAp[k], Sp[k], fmul2(dup, Bp));
        }
    }
    u64 Pp[8];
    compute_dAp(sumdl, A0, A, fast, Pp);
    int base = (c * DI + d) * DS;
    #pragma unroll
    for (int k = 0; k < 8; k++) {
        *reinterpret_cast<u64*>(&Pg[base + 2 * k]) = Pp[k];
        *reinterpret_cast<u64*>(&Sg[base + 2 * k]) = Sp[k];
    }
}

// Carry level 1: compose GRP chunks per group -> group aggregates
__global__ void k_carry1(const float* __restrict__ Pg, const float* __restrict__ Sg,
                         float* __restrict__ Pa, float* __restrict__ Sa)
{
    int idx = blockIdx.x * blockDim.x + threadIdx.x;
    int g = idx / NSEQ, i = idx % NSEQ;
    float P = 1.f, S = 0.f;
    #pragma unroll 8
    for (int t = 0; t < GRP; t++) {
        int o = (g * GRP + t) * NSEQ + i;
        float p = Pg[o], s = Sg[o];
        S = fmaf(p, S, s);
        P *= p;
    }
    Pa[g * NSEQ + i] = P;
    Sa[g * NSEQ + i] = S;
}

// Carry level 2: serial scan over NGRP group aggregates
__global__ void k_carry2(const float* __restrict__ Pa, const float* __restrict__ Sa,
                         float* __restrict__ G)
{
    int i = blockIdx.x * blockDim.x + threadIdx.x;
    float H = 0.f;
    for (int g = 0; g < NGRP; g++) {
        G[g * NSEQ + i] = H;
        H = fmaf(Pa[g * NSEQ + i], H, Sa[g * NSEQ + i]);
    }
}

// Carry level 3: expand group-start H to per-chunk H0
__global__ void k_carry3(const float* __restrict__ Pg, const float* __restrict__ Sg,
                         const float* __restrict__ G, float* __restrict__ H0)
{
    int idx = blockIdx.x * blockDim.x + threadIdx.x;
    int g = idx / NSEQ, i = idx % NSEQ;
    float H = G[g * NSEQ + i];
    #pragma unroll 8
    for (int t = 0; t < GRP; t++) {
        int o = (g * GRP + t) * NSEQ + i;
        H0[o] = H;
        H = fmaf(Pg[o], H, Sg[o]);
    }
}

// rescan with carry, emit yz = (y + u*D) * silu(z)  (packed state)
__global__ void k_scan2(const float* __restrict__ delta, const float* __restrict__ u,
                        const float* __restrict__ bc, const float* __restrict__ Alog,
                        const float* __restrict__ H0, const float* __restrict__ Dp,
                        const float* __restrict__ xiz, float* __restrict__ yz)
{
    __shared__ __align__(16) float sD[LC * DI], sU[LC * DI], sB[LC * DS], sC[LC * DS];
    int c = blockIdx.x, d = threadIdx.x;
    int l0 = c * LC;
    const float4* gD = (const float4*)(delta + l0 * DI);
    const float4* gU = (const float4*)(u + l0 * DI);
    #pragma unroll
    for (int k = 0; k < LC * DI / 4 / 128; k++) {
        ((float4*)sD)[d + k * 128] = gD[d + k * 128];
        ((float4*)sU)[d + k * 128] = gU[d + k * 128];
    }
    for (int idx = d; idx < LC * DS; idx += 128) {
        int t = idx >> 4, s = idx & 15;
        sB[idx] = bc[(l0 + t) * 32 + s];
        sC[idx] = bc[(l0 + t) * 32 + 16 + s];
    }
    __syncthreads();

    float A[DS], A0;
    bool fast = load_A(Alog, d, A, A0);

    u64 hp[8];
    #pragma unroll
    for (int k = 0; k < 8; k++)
        hp[k] = *reinterpret_cast<const u64*>(&H0[(c * DI + d) * DS + 2 * k]);
    float Dd = Dp[d];

    #pragma unroll 2
    for (int t = 0; t < LC; t++) {
        float z = xiz[(l0 + t) * 256 + 128 + d];
        float dl = sD[t * DI + d];
        float uu = sU[t * DI + d];
        float du = dl * uu;
        u64 dAp[8];
        compute_dAp(dl, A0, A, fast, dAp);
        u64 dup = pk2(du, du);
        u64 yp0 = 0ULL, yp1 = 0ULL;
        #pragma unroll
        for (int k = 0; k < 8; k++) {
            u64 Bp = *reinterpret_cast<const u64*>(&sB[t * DS + 2 * k]);
            u64 Cp = *reinterpret_cast<const u64*>(&sC[t * DS + 2 * k]);
            hp[k] = ffma2(dAp[k], hp[k], fmul2(dup, Bp));
            if (k & 1) yp1 = ffma2(hp[k], Cp, yp1);
            else       yp0 = ffma2(hp[k], Cp, yp0);
        }
        float y0, y1, y2, y3;
        upk2(yp0, y0, y1);
        upk2(yp1, y2, y3);
        float y = (y0 + y1) + (y2 + y3);
        y = fmaf(uu, Dd, y);
        float sig = 1.f / (1.f + __expf(-z));
        yz[(l0 + t) * DI + d] = y * (z * sig);
    }
}

// ============================================================
// k_tail: out-proj + residual + LN2 + gated FFN1 + FFN2 + residual
//         + transposed output, all per 64-token tile in smem.
// ============================================================
__global__ void __launch_bounds__(256, 1)
k_tail(const float* __restrict__ yz, const float* __restrict__ x,
       const float* __restrict__ Wout, const float* __restrict__ lw,
       const float* __restrict__ lb, const float* __restrict__ Wf1,
       const float* __restrict__ Wf2, float* __restrict__ out)
{
    extern __shared__ __align__(16) float sm[];
    float* sWo = sm;                 // 128*64 = 8192
    float* sW1 = sWo + 8192;         // 64*256 = 16384
    float* sW2 = sW1 + 16384;        // 128*64 = 8192
    float* sYZ = sW2 + 8192;         // 64*128 = 8192 (yz tile; reused as gg)
    float* sT  = sYZ + 8192;         // 64*66  = 4224 (xt2 tile)
    float* sH  = sT + 4224;          // 64*66  = 4224 (hn tile; reused as out stage)
    int tid = threadIdx.x, tx = tid & 31, ty = tid >> 5;

    for (int i = tid; i < 8192; i += 256) { sWo[i] = Wout[i]; sW2[i] = Wf2[i]; }
    for (int i = tid; i < 16384; i += 256) sW1[i] = Wf1[i];
    __syncthreads();

    for (int tile = blockIdx.x; tile < NT; tile += gridDim.x) {
        int l0 = tile * 64;

        // load yz tile [64,128] and residual x tile (transposed)
        const float4* gyz = (const float4*)(yz + l0 * 128);
        #pragma unroll
        for (int k = 0; k < 8; k++)
            ((float4*)sYZ)[tid + k * 256] = gyz[tid + k * 256];
        for (int idx = tid; idx < 4096; idx += 256) {
            int c = idx >> 6, i = idx & 63;
            sT[i * 66 + c] = x[c * LTOK + l0 + i];
        }
        __syncthreads();

        // ---- ML1: out-proj  acc1 = yz @ Wout  (K=128, N=64) ----
        u64 acc1[8];
        #pragma unroll
        for (int i = 0; i < 8; i++) acc1[i] = 0ULL;
        #pragma unroll 4
        for (int k2 = 0; k2 < 128; k2 += 2) {
            float2 xv[8];
            #pragma unroll
            for (int i = 0; i < 8; i++)
                xv[i] = *reinterpret_cast<const float2*>(&sYZ[(ty * 8 + i) * 128 + k2]);
            #pragma unroll
            for (int kk = 0; kk < 2; kk++) {
                u64 wv = *reinterpret_cast<const u64*>(&sWo[(k2 + kk) * 64 + 2 * tx]);
                #pragma unroll
                for (int i = 0; i < 8; i++) {
                    float xs = kk ? xv[i].y : xv[i].x;
                    acc1[i] = ffma2(pk2(xs, xs), wv, acc1[i]);
                }
            }
        }
        __syncthreads();

        // xt2 = acc1 + residual (in sT)
        #pragma unroll
        for (int i = 0; i < 8; i++) {
            int row = ty * 8 + i, col = 2 * tx;
            float a0, a1;
            upk2(acc1[i], a0, a1);
            sT[row * 66 + col]     += a0;
            sT[row * 66 + col + 1] += a1;
        }
        __syncthreads();

        // LN2 -> sH
        {
            int r = tid >> 2, q = tid & 3;
            float s = 0.f, ss = 0.f;
            #pragma unroll
            for (int c = q * 16; c < q * 16 + 16; c++) {
                float v = sT[r * 66 + c]; s += v; ss += v * v;
            }
            s  += __shfl_xor_sync(~0u, s, 1);  ss += __shfl_xor_sync(~0u, ss, 1);
            s  += __shfl_xor_sync(~0u, s, 2);  ss += __shfl_xor_sync(~0u, ss, 2);
            float mu = s * (1.f / 64.f);
            float rs = rsqrtf(ss * (1.f / 64.f) - mu * mu + 1e-5f);
            #pragma unroll
            for (int c = q * 16; c < q * 16 + 16; c++)
                sH[r * 66 + c] = (sT[r * 66 + c] - mu) * rs * lw[c] + lb[c];
        }
        __syncthreads();

        // ---- ML2: FFN1  acc2 = hn @ Wf1  (K=64, N=256) ----
        u64 acc2[8][4];
        #pragma unroll
        for (int i = 0; i < 8; i++)
            #pragma unroll
            for (int j = 0; j < 4; j++) acc2[i][j] = 0ULL;
        #pragma unroll 4
        for (int k2 = 0; k2 < 64; k2 += 2) {
            float2 xv[8];
            #pragma unroll
            for (int i = 0; i < 8; i++)
                xv[i] = *reinterpret_cast<const float2*>(&sH[(ty * 8 + i) * 66 + k2]);
            #pragma unroll
            for (int kk = 0; kk < 2; kk++) {
                u64 wv[4];
                #pragma unroll
                for (int j = 0; j < 4; j++)
                    wv[j] = *reinterpret_cast<const u64*>(&sW1[(k2 + kk) * 256 + 2 * tx + 64 * j]);
                #pragma unroll
                for (int i = 0; i < 8; i++) {
                    float xs = kk ? xv[i].y : xv[i].x;
                    u64 xp = pk2(xs, xs);
                    #pragma unroll
                    for (int j = 0; j < 4; j++) acc2[i][j] = ffma2(xp, wv[j], acc2[i][j]);
                }
            }
        }
        __syncthreads();

        // gated silu -> gg into sYZ
        #pragma unroll
        for (int i = 0; i < 8; i++)
            #pragma unroll
            for (int j = 0; j < 2; j++) {
                float g0, g1, v0, v1;
                upk2(acc2[i][j], g0, g1);
                upk2(acc2[i][j + 2], v0, v1);
                float r0 = g0 / (1.f + __expf(-g0)) * v0;
                float r1 = g1 / (1.f + __expf(-g1)) * v1;
                *reinterpret_cast<u64*>(&sYZ[(ty * 8 + i) * 128 + 2 * tx + 64 * j]) = pk2(r0, r1);
            }
        __syncthreads();

        // ---- ML3: FFN2  acc3 = gg @ Wf2  (K=128, N=64) ----
        u64 acc3[8];
        #pragma unroll
        for (int i = 0; i < 8; i++) acc3[i] = 0ULL;
        #pragma unroll 4
        for (int k2 = 0; k2 < 128; k2 += 2) {
            float2 xv[8];
            #pragma unroll
            for (int i = 0; i < 8; i++)
                xv[i] = *reinterpret_cast<const float2*>(&sYZ[(ty * 8 + i) * 128 + k2]);
            #pragma unroll
            for (int kk = 0; kk < 2; kk++) {
                u64 wv = *reinterpret_cast<const u64*>(&sW2[(k2 + kk) * 64 + 2 * tx]);
                #pragma unroll
                for (int i = 0; i < 8; i++) {
                    float xs = kk ? xv[i].y : xv[i].x;
                    acc3[i] = ffma2(pk2(xs, xs), wv, acc3[i]);
                }
            }
        }

        // final = acc3 + xt2 -> stage in sH (safe: sH reads all done pre-ML3 sync)
        #pragma unroll
        for (int i = 0; i < 8; i++) {
            int row = ty * 8 + i, col = 2 * tx;
            float a0, a1;
            upk2(acc3[i], a0, a1);
            sH[row * 66 + col]     = a0 + sT[row * 66 + col];
            sH[row * 66 + col + 1] = a1 + sT[row * 66 + col + 1];
        }
        __syncthreads();

        // transposed coalesced store
        for (int idx = tid; idx < 4096; idx += 256) {
            int ll = idx & 63, c = idx >> 6;
            out[c * LTOK + l0 + ll] = sH[ll * 66 + c];
        }
        __syncthreads();
    }
}

// ============================================================
// launch
// ============================================================
#define SM_G1   ((64 * 256 + 64 * 64 + 64 * 65) * 4)                     // 98560
#define SM_CONV ((8192 + 8192 + 4608 + 2304 + 512 + 512) * 4)            // 97280
#define SM_TAIL ((8192 + 16384 + 8192 + 8192 + 4224 + 4224) * 4)         // 197632

extern "C" void kernel_launch(void* const* d_in, const int* in_sizes, int n_in,
                              void* d_out, int out_size)
{
    const float* x    = (const float*)d_in[0];
    const float* ln1w = (const float*)d_in[1];
    const float* ln1b = (const float*)d_in[2];
    const float* Win  = (const float*)d_in[3];
    const float* cw   = (const float*)d_in[4];
    const float* Wxp  = (const float*)d_in[5];
    const float* Wdt  = (const float*)d_in[6];
    const float* dtb  = (const float*)d_in[7];
    const float* Alog = (const float*)d_in[8];
    const float* Dssm = (const float*)d_in[9];
    const float* Wout = (const float*)d_in[10];
    const float* ln2w = (const float*)d_in[11];
    const float* ln2b = (const float*)d_in[12];
    const float* Wf1  = (const float*)d_in[13];
    const float* Wf2  = (const float*)d_in[14];
    float* out = (float*)d_out;

    float* sc = nullptr;
    cudaGetSymbolAddress((void**)&sc, g_scratch);

    float* xiz   = sc + OFF_XIZ;
    float* xc    = sc + OFF_XC;
    float* delta = sc + OFF_DELTA;
    float* bcb   = sc + OFF_BC;
    float* Pg    = sc + OFF_P;
    float* Sg    = sc + OFF_S;
    float* H0    = sc + OFF_H0;
    float* Pa    = sc + OFF_PA;
    float* Sa    = sc + OFF_SA;
    float* Gb    = sc + OFF_G;
    float* yzb   = sc + OFF_YZ;

    cudaFuncSetAttribute(k_gemm1, cudaFuncAttributeMaxDynamicSharedMemorySize, SM_G1);
    cudaFuncSetAttribute(k_conv2, cudaFuncAttributeMaxDynamicSharedMemorySize, SM_CONV);
    cudaFuncSetAttribute(k_tail,  cudaFuncAttributeMaxDynamicSharedMemorySize, SM_TAIL);

    // 1. (LN1 fused) x -> xn @ W_in -> xi | z
    k_gemm1<<<296, 256, SM_G1>>>(x, Win, xiz, ln1w, ln1b);
    // 2. conv + relu + xproj + delta + chunk-local scan (fused)
    k_conv2<<<NT, 256, SM_CONV>>>(xiz, cw, Wxp, Wdt, dtb, Alog, xc, delta, bcb, Pg, Sg);
    // 3. hierarchical carry
    k_carry1<<<NGRP * NSEQ / 256, 256>>>(Pg, Sg, Pa, Sa);
    k_carry2<<<NSEQ / 256, 256>>>(Pa, Sa, Gb);
    k_carry3<<<NGRP * NSEQ / 256, 256>>>(Pg, Sg, Gb, H0);
    // 4. rescan + gate
    k_scan2<<<NCH, 128>>>(delta, xc, bcb, Alog, H0, Dssm, xiz, yzb);
    // 5. out-proj + LN2 + FFN1 + FFN2 + residuals + transposed out (fused)
    k_tail<<<148, 256, SM_TAIL>>>(yzb, x, Wout, ln2w, ln2b, Wf1, Wf2, out);
}